// round 13
// baseline (speedup 1.0000x reference)
#include <cuda_runtime.h>
#include <cuda_fp16.h>
#include <stdint.h>

#define D_MODEL 1024
#define NHEAD   16
#define DK      64
#define BATCH   2
#define SEQ     2048
#define MTOT    (BATCH*SEQ)   // 4096
#define NELEM   ((size_t)MTOT*D_MODEL)

// ---------------- scratch (static device globals; no allocations) ----------
__device__ __half g_qh[NELEM],    g_ql[NELEM];
__device__ __half g_kh[NELEM],    g_kl[NELEM];
__device__ __half g_vh[NELEM],    g_vl[NELEM];
__device__ __half g_wqh[(size_t)D_MODEL*D_MODEL], g_wql[(size_t)D_MODEL*D_MODEL];
__device__ __half g_wkh[(size_t)D_MODEL*D_MODEL], g_wkl[(size_t)D_MODEL*D_MODEL];
__device__ __half g_wvh[(size_t)D_MODEL*D_MODEL], g_wvl[(size_t)D_MODEL*D_MODEL];
__device__ __half g_woh[(size_t)D_MODEL*D_MODEL], g_wol[(size_t)D_MODEL*D_MODEL];
// projected tensors, head-major [b][h][s][d]; merged arrays
__device__ __half g_pq [2][NELEM];          // Q hi/lo (pre-scaled 0.125*log2e)
__device__ __half g_pkv[4][NELEM];          // Kh, Kl, Vh, Vl
__device__ __half g_po [2][NELEM];          // attn out hi/lo [b][s][h*64+d]

// ======================= low-level helpers (base ISA only) ================
__device__ __forceinline__ unsigned smem_u32(const void* p) {
    unsigned a;
    asm("{ .reg .u64 t; cvta.to.shared.u64 t, %1; cvt.u32.u64 %0, t; }" : "=r"(a) : "l"(p));
    return a;
}
__device__ __forceinline__ void cp16(unsigned dst, const void* src) {
    asm volatile("cp.async.cg.shared.global [%0], [%1], 16;" :: "r"(dst), "l"(src));
}
#define CP_COMMIT() asm volatile("cp.async.commit_group;" ::: "memory")
#define CP_WAIT1()  asm volatile("cp.async.wait_group 1;"  ::: "memory")
#define CP_WAIT0()  asm volatile("cp.async.wait_group 0;"  ::: "memory")

#define LDSM4(r, a) \
    asm volatile("ldmatrix.sync.aligned.m8n8.x4.shared.b16 {%0,%1,%2,%3}, [%4];" \
        : "=r"((r)[0]), "=r"((r)[1]), "=r"((r)[2]), "=r"((r)[3]) : "r"(a))
#define LDSM4T(r, a) \
    asm volatile("ldmatrix.sync.aligned.m8n8.x4.trans.shared.b16 {%0,%1,%2,%3}, [%4];" \
        : "=r"((r)[0]), "=r"((r)[1]), "=r"((r)[2]), "=r"((r)[3]) : "r"(a))

// fp16 inputs, f32 accumulate (hi*hi term)
#define MMA4F(d, a, b0, b1) \
    asm volatile("mma.sync.aligned.m16n8k16.row.col.f32.f16.f16.f32 " \
        "{%0,%1,%2,%3}, {%4,%5,%6,%7}, {%8,%9}, {%0,%1,%2,%3};" \
        : "+f"((d)[0]), "+f"((d)[1]), "+f"((d)[2]), "+f"((d)[3]) \
        : "r"((a)[0]), "r"((a)[1]), "r"((a)[2]), "r"((a)[3]), "r"(b0), "r"(b1))

// fp16 inputs, f16 accumulate (cross terms; full-rate pipe)
#define MMAH(d, a, b0, b1) \
    asm volatile("mma.sync.aligned.m16n8k16.row.col.f16.f16.f16.f16 " \
        "{%0,%1}, {%2,%3,%4,%5}, {%6,%7}, {%0,%1};" \
        : "+r"((d)[0]), "+r"((d)[1]) \
        : "r"((a)[0]), "r"((a)[1]), "r"((a)[2]), "r"((a)[3]), "r"(b0), "r"(b1))

__device__ __forceinline__ float fexp2(float x) {
    float y; asm("ex2.approx.f32 %0, %1;" : "=f"(y) : "f"(x)); return y;
}
// fp16 hi/lo split of an fp32 pair
__device__ __forceinline__ void split2h(float x, float y, unsigned& hi, unsigned& lo) {
    __half2 h = __float22half2_rn(make_float2(x, y));
    float2 hf = __half22float2(h);
    __half2 l = __float22half2_rn(make_float2(x - hf.x, y - hf.y));
    hi = *(unsigned*)&h; lo = *(unsigned*)&l;
}
// merge a 2-reg f16 accumulator tile into a 4-float f32 accumulator tile
__device__ __forceinline__ void merge2(float* a, unsigned t0, unsigned t1) {
    float2 f0 = __half22float2(*reinterpret_cast<const __half2*>(&t0));
    float2 f1 = __half22float2(*reinterpret_cast<const __half2*>(&t1));
    a[0] += f0.x; a[1] += f0.y; a[2] += f1.x; a[3] += f1.y;
}

// ======================= split kernel: fp32 -> fp16 hi/lo ===================
__global__ __launch_bounds__(256) void split_all(
    const float* q, const float* k, const float* v,
    const float* wq, const float* wk, const float* wv, const float* wo)
{
    const int z = blockIdx.y;
    const float* src; __half *dh, *dl; int n4;
    const int NA = MTOT*D_MODEL/4, NW = D_MODEL*D_MODEL/4;
    switch (z) {
        case 0: src = q;  dh = g_qh;  dl = g_ql;  n4 = NA; break;
        case 1: src = k;  dh = g_kh;  dl = g_kl;  n4 = NA; break;
        case 2: src = v;  dh = g_vh;  dl = g_vl;  n4 = NA; break;
        case 3: src = wq; dh = g_wqh; dl = g_wql; n4 = NW; break;
        case 4: src = wk; dh = g_wkh; dl = g_wkl; n4 = NW; break;
        case 5: src = wv; dh = g_wvh; dl = g_wvl; n4 = NW; break;
        default:src = wo; dh = g_woh; dl = g_wol; n4 = NW; break;
    }
    for (int i = blockIdx.x * blockDim.x + threadIdx.x; i < n4; i += gridDim.x * blockDim.x) {
        float4 vv = ((const float4*)src)[i];
        unsigned h0, l0, h1, l1;
        split2h(vv.x, vv.y, h0, l0);
        split2h(vv.z, vv.w, h1, l1);
        ((unsigned*)dh)[2*i] = h0; ((unsigned*)dh)[2*i+1] = h1;
        ((unsigned*)dl)[2*i] = l0; ((unsigned*)dl)[2*i+1] = l1;
    }
}

// ======================= HMMA GEMM core (fp16 split, mixed accum) ==========
// BM=BN=128, BK=32, 256 thr (8 warps = 4x2), warp tile 32x64, 3 stages.
// Per step: hi*hi -> f32-acc MMA; hi*lo + lo*hi -> chained f16-acc MMAs,
// merged into the f32 accumulator immediately (transient 8 regs).
#define G_STAGE 32768
#define G_SMEM  (3*G_STAGE)

__device__ __forceinline__ void gemm_load_stage(
    unsigned st, const __half* Ah, const __half* Al,
    const __half* Bh, const __half* Bl,
    int m0, int n0, int k0, int tid)
{
    const __half* srcs[4] = {Ah, Al, Bh, Bl};
    #pragma unroll
    for (int tt = 0; tt < 4; ++tt) {
        const int r0 = (tt < 2) ? m0 : n0;
        const __half* s = srcs[tt];
        #pragma unroll
        for (int i = 0; i < 2; ++i) {
            int idx = tid + i * 256;
            int row = idx >> 2, kc = idx & 3;
            unsigned d = st + tt * 8192 + row * 64 + (((kc ^ ((row >> 1) & 3))) << 4);
            cp16(d, s + (size_t)(r0 + row) * D_MODEL + k0 + kc * 8);
        }
    }
}

__device__ __forceinline__ void gemm_compute(
    const __half* Ah, const __half* Al,
    const __half* Bh, const __half* Bl,
    int m0, int n0, unsigned sb, int tid, float acc[2][8][4])
{
    const int lane = tid & 31, wid = tid >> 5;
    const int wm = wid & 3, wn = wid >> 2;

    gemm_load_stage(sb,            Ah, Al, Bh, Bl, m0, n0, 0,  tid); CP_COMMIT();
    gemm_load_stage(sb + G_STAGE,  Ah, Al, Bh, Bl, m0, n0, 32, tid); CP_COMMIT();

    for (int it = 0; it < 32; ++it) {
        CP_WAIT1();
        __syncthreads();
        if (it + 2 < 32)
            gemm_load_stage(sb + ((it + 2) % 3) * G_STAGE, Ah, Al, Bh, Bl,
                            m0, n0, (it + 2) * 32, tid);
        CP_COMMIT();
        const unsigned st = sb + (it % 3) * G_STAGE;
        #pragma unroll
        for (int ks = 0; ks < 2; ++ks) {
            unsigned aH[2][4], aL[2][4];
            #pragma unroll
            for (int mt = 0; mt < 2; ++mt) {
                int row = wm * 32 + mt * 16 + (lane & 15);
                int kc  = 2 * ks + (lane >> 4);
                unsigned off = row * 64 + (((kc ^ ((row >> 1) & 3))) << 4);
                LDSM4(aH[mt], st + off);
                LDSM4(aL[mt], st + 8192 + off);
            }
            #pragma unroll
            for (int q = 0; q < 4; ++q) {
                unsigned bH[4], bL[4];
                int row = wn * 64 + q * 16 + (lane & 7) + 8 * ((lane >> 4) & 1);
                int kc  = 2 * ks + ((lane >> 3) & 1);
                unsigned off = row * 64 + (((kc ^ ((row >> 1) & 3))) << 4);
                LDSM4(bH, st + 16384 + off);
                LDSM4(bL, st + 24576 + off);
                // hi*hi -> f32 acc
                MMA4F(acc[0][2*q],   aH[0], bH[0], bH[1]);
                MMA4F(acc[1][2*q],   aH[1], bH[0], bH[1]);
                MMA4F(acc[0][2*q+1], aH[0], bH[2], bH[3]);
                MMA4F(acc[1][2*q+1], aH[1], bH[2], bH[3]);
                // cross terms -> f16 acc (chained), then merge
                unsigned t0[2] = {0,0}, t1[2] = {0,0}, t2[2] = {0,0}, t3[2] = {0,0};
                MMAH(t0, aH[0], bL[0], bL[1]);
                MMAH(t1, aH[1], bL[0], bL[1]);
                MMAH(t2, aH[0], bL[2], bL[3]);
                MMAH(t3, aH[1], bL[2], bL[3]);
                MMAH(t0, aL[0], bH[0], bH[1]);
                MMAH(t1, aL[1], bH[0], bH[1]);
                MMAH(t2, aL[0], bH[2], bH[3]);
                MMAH(t3, aL[1], bH[2], bH[3]);
                merge2(acc[0][2*q],   t0[0], t0[1]);
                merge2(acc[1][2*q],   t1[0], t1[1]);
                merge2(acc[0][2*q+1], t2[0], t2[1]);
                merge2(acc[1][2*q+1], t3[0], t3[1]);
            }
        }
    }
}

// ---------------- QKV projection: grid (8, 32, 3), 256 thr -----------------
__global__ void __launch_bounds__(256, 2) tc_qkv(
    const float* __restrict__ bq, const float* __restrict__ bk,
    const float* __restrict__ bv)
{
    extern __shared__ char smem[];
    const unsigned sb = smem_u32(smem);
    const int z = blockIdx.z;
    const __half *Ah, *Al, *Bh, *Bl;
    __half *dh, *dl;
    const float* bias;
    float scale;
    if (z == 0)      { Ah=g_qh; Al=g_ql; Bh=g_wqh; Bl=g_wql; dh=g_pq[0];  dl=g_pq[1];  bias=bq; scale=0.18033688f; }
    else if (z == 1) { Ah=g_kh; Al=g_kl; Bh=g_wkh; Bl=g_wkl; dh=g_pkv[0]; dl=g_pkv[1]; bias=bk; scale=1.0f; }
    else             { Ah=g_vh; Al=g_vl; Bh=g_wvh; Bl=g_wvl; dh=g_pkv[2]; dl=g_pkv[3]; bias=bv; scale=1.0f; }

    const int n0 = blockIdx.x * 128, m0 = blockIdx.y * 128;
    const int tid = threadIdx.x, lane = tid & 31, wid = tid >> 5;
    const int wm = wid & 3, wn = wid >> 2;

    float acc[2][8][4] = {};
    gemm_compute(Ah, Al, Bh, Bl, m0, n0, sb, tid, acc);

    #pragma unroll
    for (int nt = 0; nt < 8; ++nt) {
        int n = n0 + wn * 64 + nt * 8 + (lane & 3) * 2;
        float b0v = bias[n], b1v = bias[n + 1];
        int hd = n >> 6, d = n & 63;
        #pragma unroll
        for (int mt = 0; mt < 2; ++mt) {
            #pragma unroll
            for (int half = 0; half < 2; ++half) {
                int m = m0 + wm * 32 + mt * 16 + (lane >> 2) + 8 * half;
                float x = (acc[mt][nt][2*half+0] + b0v) * scale;
                float y = (acc[mt][nt][2*half+1] + b1v) * scale;
                unsigned hi, lo; split2h(x, y, hi, lo);
                size_t dst = ((size_t)((m >> 11) * NHEAD + hd) * SEQ + (m & (SEQ-1))) * DK + d;
                *(unsigned*)(dh + dst) = hi;
                *(unsigned*)(dl + dst) = lo;
            }
        }
    }
}

// ---------------- output projection: grid (8, 32), 256 thr -----------------
__global__ void __launch_bounds__(256, 2) tc_out(
    const float* __restrict__ bias, float* __restrict__ out)
{
    extern __shared__ char smem[];
    const unsigned sb = smem_u32(smem);
    const int n0 = blockIdx.x * 128, m0 = blockIdx.y * 128;
    const int tid = threadIdx.x, lane = tid & 31, wid = tid >> 5;
    const int wm = wid & 3, wn = wid >> 2;

    float acc[2][8][4] = {};
    gemm_compute(g_po[0], g_po[1], g_woh, g_wol, m0, n0, sb, tid, acc);

    #pragma unroll
    for (int nt = 0; nt < 8; ++nt) {
        int n = n0 + wn * 64 + nt * 8 + (lane & 3) * 2;
        float b0v = bias[n], b1v = bias[n + 1];
        #pragma unroll
        for (int mt = 0; mt < 2; ++mt) {
            #pragma unroll
            for (int half = 0; half < 2; ++half) {
                int m = m0 + wm * 32 + mt * 16 + (lane >> 2) + 8 * half;
                float2 vv = make_float2(acc[mt][nt][2*half+0] + b0v,
                                        acc[mt][nt][2*half+1] + b1v);
                *(float2*)(out + (size_t)m * D_MODEL + n) = vv;
            }
        }
    }
}

// ---------------- flash attention on HMMA: grid (32, 16, 2), 128 thr -------
// Br=64 (warp w owns rows 16w..16w+15), Bc=32, 64 KV tiles.
// Q fragments in registers. SMEM: 3 KV stages x 16KB = 48KB.
// hi*hi -> f32 acc; cross terms -> chained f16 acc, merged per section.
#define A_STAGE 16384
#define A_SMEM  (3*A_STAGE)

__device__ __forceinline__ void attn_load_stage(
    unsigned st, const __half* kvbase, int tid)
{
    #pragma unroll
    for (int tt = 0; tt < 4; ++tt) {
        const __half* s = kvbase + (size_t)tt * NELEM;
        #pragma unroll
        for (int i = 0; i < 2; ++i) {
            int idx = tid + i * 128;         // 0..255 chunks (32 rows x 8)
            int row = idx >> 3, dc = idx & 7;
            unsigned d = st + tt * 4096 + row * 128 + (((dc ^ (row & 7))) << 4);
            cp16(d, s + (size_t)row * DK + dc * 8);
        }
    }
}

__global__ void __launch_bounds__(128, 2) attn_mma() {
    extern __shared__ char smem[];
    const unsigned sb = smem_u32(smem);
    const int tid = threadIdx.x, lane = tid & 31, w = tid >> 5;
    const int qt = blockIdx.x, h = blockIdx.y, b = blockIdx.z;

    const size_t headoff = ((size_t)(b * NHEAD + h)) * SEQ * DK;
    const __half* qbase  = &g_pq[0][0]  + headoff + (size_t)qt * 64 * DK;
    const __half* kvbase = &g_pkv[0][0] + headoff;

    // ---- prologue: stage Q through smem stages 0/1, park fragments in regs -
    #pragma unroll
    for (int tile = 0; tile < 2; ++tile)
        #pragma unroll
        for (int i = 0; i < 4; ++i) {
            int idx = tid + i * 128;         // 0..511 (64 rows x 8)
            int row = idx >> 3, dc = idx & 7;
            cp16(sb + tile * 8192 + row * 128 + (((dc ^ (row & 7))) << 4),
                 qbase + (size_t)tile * NELEM + (size_t)row * DK + dc * 8);
        }
    CP_COMMIT(); CP_WAIT0();
    __syncthreads();

    unsigned qh_f[4][4], ql_f[4][4];
    #pragma unroll
    for (int ks = 0; ks < 4; ++ks) {
        int row = 16 * w + (lane & 15);
        int dc  = 2 * ks + (lane >> 4);
        unsigned off = row * 128 + (((dc ^ (row & 7))) << 4);
        LDSM4(qh_f[ks], sb + off);
        LDSM4(ql_f[ks], sb + 8192 + off);
    }
    __syncthreads();   // stage-0/1 free before KV pipeline reuses them

    attn_load_stage(sb,           kvbase, tid);            CP_COMMIT();
    attn_load_stage(sb + A_STAGE, kvbase + 32 * DK, tid);  CP_COMMIT();

    float s_m[2] = {-1e30f, -1e30f}, s_l[2] = {0.f, 0.f};
    float o[8][4] = {};

    for (int t = 0; t < 64; ++t) {
        CP_WAIT1();
        __syncthreads();
        if (t + 2 < 64)
            attn_load_stage(sb + ((t + 2) % 3) * A_STAGE,
                            kvbase + (size_t)(t + 2) * 32 * DK, tid);
        CP_COMMIT();
        const unsigned st = sb + (t % 3) * A_STAGE;

        // ---- S = Q K^T (Q pre-scaled by 0.125*log2e) ----
        float s[4][4] = {};
        #pragma unroll
        for (int ks = 0; ks < 4; ++ks) {
            unsigned bh[2][4], bl[2][4];
            #pragma unroll
            for (int q4 = 0; q4 < 2; ++q4) {
                int krow = q4 * 16 + (lane & 7) + 8 * ((lane >> 4) & 1);
                int kdc  = 2 * ks + ((lane >> 3) & 1);
                unsigned off = krow * 128 + (((kdc ^ (krow & 7))) << 4);
                LDSM4(bh[q4], st + off);
                LDSM4(bl[q4], st + 4096 + off);
            }
            // hi*hi -> f32
            MMA4F(s[0], qh_f[ks], bh[0][0], bh[0][1]);
            MMA4F(s[1], qh_f[ks], bh[0][2], bh[0][3]);
            MMA4F(s[2], qh_f[ks], bh[1][0], bh[1][1]);
            MMA4F(s[3], qh_f[ks], bh[1][2], bh[1][3]);
            // cross terms -> f16, merge
            unsigned u0[2]={0,0}, u1[2]={0,0}, u2[2]={0,0}, u3[2]={0,0};
            MMAH(u0, qh_f[ks], bl[0][0], bl[0][1]);
            MMAH(u1, qh_f[ks], bl[0][2], bl[0][3]);
            MMAH(u2, qh_f[ks], bl[1][0], bl[1][1]);
            MMAH(u3, qh_f[ks], bl[1][2], bl[1][3]);
            MMAH(u0, ql_f[ks], bh[0][0], bh[0][1]);
            MMAH(u1, ql_f[ks], bh[0][2], bh[0][3]);
            MMAH(u2, ql_f[ks], bh[1][0], bh[1][1]);
            MMAH(u3, ql_f[ks], bh[1][2], bh[1][3]);
            merge2(s[0], u0[0], u0[1]);
            merge2(s[1], u1[0], u1[1]);
            merge2(s[2], u2[0], u2[1]);
            merge2(s[3], u3[0], u3[1]);
        }

        // ---- online softmax (base-2 domain) ----
        #pragma unroll
        for (int r = 0; r < 2; ++r) {
            float mx = -1e30f;
            #pragma unroll
            for (int nt = 0; nt < 4; ++nt)
                mx = fmaxf(mx, fmaxf(s[nt][2*r], s[nt][2*r+1]));
            mx = fmaxf(mx, __shfl_xor_sync(0xffffffffu, mx, 1));
            mx = fmaxf(mx, __shfl_xor_sync(0xffffffffu, mx, 2));
            float mnew  = fmaxf(s_m[r], mx);
            float alpha = fexp2(s_m[r] - mnew);
            float rs = 0.f;
            #pragma unroll
            for (int nt = 0; nt < 4; ++nt) {
                float p0 = fexp2(s[nt][2*r]   - mnew);
                float p1 = fexp2(s[nt][2*r+1] - mnew);
                s[nt][2*r] = p0; s[nt][2*r+1] = p1;
                rs += p0 + p1;
            }
            rs += __shfl_xor_sync(0xffffffffu, rs, 1);
            rs += __shfl_xor_sync(0xffffffffu, rs, 2);
            s_l[r] = s_l[r] * alpha + rs;
            s_m[r] = mnew;
            #pragma unroll
            for (int nt = 0; nt < 8; ++nt) { o[nt][2*r] *= alpha; o[nt][2*r+1] *= alpha; }
        }

        // ---- O += P V (P split to fp16 hi/lo; mixed-accum terms) ----
        #pragma unroll
        for (int ks = 0; ks < 2; ++ks) {
            unsigned pa_h[4], pa_l[4];
            #pragma unroll
            for (int e = 0; e < 4; ++e) {
                int nt = 2 * ks + (e >> 1);
                float x = s[nt][(e & 1) * 2], y = s[nt][(e & 1) * 2 + 1];
                split2h(x, y, pa_h[e], pa_l[e]);
            }
            #pragma unroll
            for (int dd = 0; dd < 4; dd += 2) {
                unsigned vh0[4], vl0[4], vh1[4], vl1[4];
                int vrow = 16 * ks + (lane & 15);
                {
                    int vdc = 2 * dd + (lane >> 4);
                    unsigned off = vrow * 128 + (((vdc ^ (vrow & 7))) << 4);
                    LDSM4T(vh0, st + 8192  + off);
                    LDSM4T(vl0, st + 12288 + off);
                }
                {
                    int vdc = 2 * (dd + 1) + (lane >> 4);
                    unsigned off = vrow * 128 + (((vdc ^ (vrow & 7))) << 4);
                    LDSM4T(vh1, st + 8192  + off);
                    LDSM4T(vl1, st + 12288 + off);
                }
                // hi*hi -> f32
                MMA4F(o[2*dd],   pa_h, vh0[0], vh0[1]);
                MMA4F(o[2*dd+1], pa_h, vh0[2], vh0[3]);
                MMA4F(o[2*dd+2], pa_h, vh1[0], vh1[1]);
                MMA4F(o[2*dd+3], pa_h, vh1[2], vh1[3]);
                // cross terms -> f16, merge
                unsigned u0[2]={0,0}, u1[2]={0,0}, u2[2]={0,0}, u3[2]={0,0};
                MMAH(u0, pa_h, vl0[0], vl0[1]);
                MMAH(u1, pa_h, vl0[2], vl0[3]);
                MMAH(u2, pa_h, vl1[0], vl1[1]);
                MMAH(u3, pa_h, vl1[2], vl1[3]);
                MMAH(u0, pa_l, vh0[0], vh0[1]);
                MMAH(u1, pa_l, vh0[2], vh0[3]);
                MMAH(u2, pa_l, vh1[0], vh1[1]);
                MMAH(u3, pa_l, vh1[2], vh1[3]);
                merge2(o[2*dd],   u0[0], u0[1]);
                merge2(o[2*dd+1], u1[0], u1[1]);
                merge2(o[2*dd+2], u2[0], u2[1]);
                merge2(o[2*dd+3], u3[0], u3[1]);
            }
        }
    }

    // ---- epilogue: O/l, split to fp16 h/l at [b][s][h*64+d] ----
    float inv[2] = {1.f / s_l[0], 1.f / s_l[1]};
    __half* pobase = &g_po[0][0];
    #pragma unroll
    for (int nt = 0; nt < 8; ++nt) {
        int d = h * DK + nt * 8 + (lane & 3) * 2;
        #pragma unroll
        for (int r = 0; r < 2; ++r) {
            int srow = qt * 64 + 16 * w + (lane >> 2) + 8 * r;
            float x = o[nt][2*r] * inv[r], y = o[nt][2*r+1] * inv[r];
            unsigned hi, lo; split2h(x, y, hi, lo);
            size_t dst = (size_t)(b * SEQ + srow) * D_MODEL + d;
            *(unsigned*)(pobase + dst)         = hi;
            *(unsigned*)(pobase + NELEM + dst) = lo;
        }
    }
}

// ---------------- launcher --------------------------------------------------
extern "C" void kernel_launch(void* const* d_in, const int* in_sizes, int n_in,
                              void* d_out, int out_size) {
    const float* query = (const float*)d_in[0];
    const float* key   = (const float*)d_in[1];
    const float* value = (const float*)d_in[2];
    const float* Wq    = (const float*)d_in[3];
    const float* bq    = (const float*)d_in[4];
    const float* Wk    = (const float*)d_in[5];
    const float* bk    = (const float*)d_in[6];
    const float* Wv    = (const float*)d_in[7];
    const float* bv    = (const float*)d_in[8];
    const float* Wo    = (const float*)d_in[9];
    const float* bo    = (const float*)d_in[10];
    float* out = (float*)d_out;

    cudaFuncSetAttribute(tc_qkv,   cudaFuncAttributeMaxDynamicSharedMemorySize, G_SMEM);
    cudaFuncSetAttribute(tc_out,   cudaFuncAttributeMaxDynamicSharedMemorySize, G_SMEM);
    cudaFuncSetAttribute(attn_mma, cudaFuncAttributeMaxDynamicSharedMemorySize, A_SMEM);

    dim3 gS(592, 7);
    split_all<<<gS, 256>>>(query, key, value, Wq, Wk, Wv, Wo);

    dim3 gQKV(D_MODEL / 128, MTOT / 128, 3);   // (8, 32, 3)
    tc_qkv<<<gQKV, 256, G_SMEM>>>(bq, bk, bv);

    dim3 gAtt(SEQ / 64, NHEAD, BATCH);         // (32, 16, 2)
    attn_mma<<<gAtt, 128, A_SMEM>>>();

    dim3 gOut(D_MODEL / 128, MTOT / 128, 1);   // (8, 32)
    tc_out<<<gOut, 256, G_SMEM>>>(bo, out);
}

// round 14
// speedup vs baseline: 1.6454x; 1.6454x over previous
#include <cuda_runtime.h>
#include <cuda_fp16.h>
#include <stdint.h>

#define D_MODEL 1024
#define NHEAD   16
#define DK      64
#define BATCH   2
#define SEQ     2048
#define MTOT    (BATCH*SEQ)   // 4096
#define NELEM   ((size_t)MTOT*D_MODEL)
#define NW      ((size_t)D_MODEL*D_MODEL)

// ---------------- scratch (static device globals; no allocations) ----------
// activations: fp16 hi only (A-side of their GEMMs)
__device__ __half g_qh[NELEM], g_kh[NELEM], g_vh[NELEM];
// weights: fp16 hi+lo (B-side)
__device__ __half g_wqh[NW], g_wql[NW];
__device__ __half g_wkh[NW], g_wkl[NW];
__device__ __half g_wvh[NW], g_wvl[NW];
__device__ __half g_woh[NW], g_wol[NW];
// projected tensors, head-major [b][h][s][d]
__device__ __half g_pq [NELEM];            // Q hi only (pre-scaled 0.125*log2e)
__device__ __half g_pkv[4][NELEM];         // Kh, Kl, Vh, Vl
__device__ __half g_po [NELEM];            // attn out hi only [b][s][h*64+d]

// ======================= low-level helpers (base ISA only) ================
__device__ __forceinline__ unsigned smem_u32(const void* p) {
    unsigned a;
    asm("{ .reg .u64 t; cvta.to.shared.u64 t, %1; cvt.u32.u64 %0, t; }" : "=r"(a) : "l"(p));
    return a;
}
__device__ __forceinline__ void cp16(unsigned dst, const void* src) {
    asm volatile("cp.async.cg.shared.global [%0], [%1], 16;" :: "r"(dst), "l"(src));
}
#define CP_COMMIT() asm volatile("cp.async.commit_group;" ::: "memory")
#define CP_WAIT1()  asm volatile("cp.async.wait_group 1;"  ::: "memory")
#define CP_WAIT0()  asm volatile("cp.async.wait_group 0;"  ::: "memory")

#define LDSM4(r, a) \
    asm volatile("ldmatrix.sync.aligned.m8n8.x4.shared.b16 {%0,%1,%2,%3}, [%4];" \
        : "=r"((r)[0]), "=r"((r)[1]), "=r"((r)[2]), "=r"((r)[3]) : "r"(a))
#define LDSM4T(r, a) \
    asm volatile("ldmatrix.sync.aligned.m8n8.x4.trans.shared.b16 {%0,%1,%2,%3}, [%4];" \
        : "=r"((r)[0]), "=r"((r)[1]), "=r"((r)[2]), "=r"((r)[3]) : "r"(a))

// fp16 inputs, f32 accumulate
#define MMA4F(d, a, b0, b1) \
    asm volatile("mma.sync.aligned.m16n8k16.row.col.f32.f16.f16.f32 " \
        "{%0,%1,%2,%3}, {%4,%5,%6,%7}, {%8,%9}, {%0,%1,%2,%3};" \
        : "+f"((d)[0]), "+f"((d)[1]), "+f"((d)[2]), "+f"((d)[3]) \
        : "r"((a)[0]), "r"((a)[1]), "r"((a)[2]), "r"((a)[3]), "r"(b0), "r"(b1))

__device__ __forceinline__ float fexp2(float x) {
    float y; asm("ex2.approx.f32 %0, %1;" : "=f"(y) : "f"(x)); return y;
}
__device__ __forceinline__ unsigned pack_h2(float x, float y) {
    __half2 h = __float22half2_rn(make_float2(x, y));
    return *(unsigned*)&h;
}
// fp16 hi/lo split of an fp32 pair
__device__ __forceinline__ void split2h(float x, float y, unsigned& hi, unsigned& lo) {
    __half2 h = __float22half2_rn(make_float2(x, y));
    float2 hf = __half22float2(h);
    __half2 l = __float22half2_rn(make_float2(x - hf.x, y - hf.y));
    hi = *(unsigned*)&h; lo = *(unsigned*)&l;
}

// ======================= split kernel ======================================
// z<3: activations -> fp16 hi only. z>=3: weights -> fp16 hi+lo.
__global__ __launch_bounds__(256) void split_all(
    const float* q, const float* k, const float* v,
    const float* wq, const float* wk, const float* wv, const float* wo)
{
    const int z = blockIdx.y;
    const float* src; __half *dh, *dl = 0; int n4;
    const int NA4 = MTOT*D_MODEL/4, NW4 = D_MODEL*D_MODEL/4;
    switch (z) {
        case 0: src = q;  dh = g_qh;  n4 = NA4; break;
        case 1: src = k;  dh = g_kh;  n4 = NA4; break;
        case 2: src = v;  dh = g_vh;  n4 = NA4; break;
        case 3: src = wq; dh = g_wqh; dl = g_wql; n4 = NW4; break;
        case 4: src = wk; dh = g_wkh; dl = g_wkl; n4 = NW4; break;
        case 5: src = wv; dh = g_wvh; dl = g_wvl; n4 = NW4; break;
        default:src = wo; dh = g_woh; dl = g_wol; n4 = NW4; break;
    }
    if (z < 3) {
        for (int i = blockIdx.x * blockDim.x + threadIdx.x; i < n4; i += gridDim.x * blockDim.x) {
            float4 vv = ((const float4*)src)[i];
            uint2 o;
            o.x = pack_h2(vv.x, vv.y);
            o.y = pack_h2(vv.z, vv.w);
            ((uint2*)dh)[i] = o;
        }
    } else {
        for (int i = blockIdx.x * blockDim.x + threadIdx.x; i < n4; i += gridDim.x * blockDim.x) {
            float4 vv = ((const float4*)src)[i];
            unsigned h0, l0, h1, l1;
            split2h(vv.x, vv.y, h0, l0);
            split2h(vv.z, vv.w, h1, l1);
            ((unsigned*)dh)[2*i] = h0; ((unsigned*)dh)[2*i+1] = h1;
            ((unsigned*)dl)[2*i] = l0; ((unsigned*)dl)[2*i+1] = l1;
        }
    }
}

// ======================= HMMA GEMM core (2-term fp16 split) ================
// C = Ah*Bh + Ah*Bl. BM=BN=128, BK=32, 256 thr (8 warps = 4x2),
// warp tile 32x64, 3 stages. Stage 24KB: Ah@0, Bh@8K, Bl@16K.
#define G_STAGE 24576
#define G_SMEM  (3*G_STAGE)

__device__ __forceinline__ void gemm_load_stage(
    unsigned st, const __half* Ah, const __half* Bh, const __half* Bl,
    int m0, int n0, int k0, int tid)
{
    const __half* srcs[3] = {Ah, Bh, Bl};
    #pragma unroll
    for (int tt = 0; tt < 3; ++tt) {
        const int r0 = (tt == 0) ? m0 : n0;
        const __half* s = srcs[tt];
        #pragma unroll
        for (int i = 0; i < 2; ++i) {
            int idx = tid + i * 256;
            int row = idx >> 2, kc = idx & 3;
            unsigned d = st + tt * 8192 + row * 64 + (((kc ^ ((row >> 1) & 3))) << 4);
            cp16(d, s + (size_t)(r0 + row) * D_MODEL + k0 + kc * 8);
        }
    }
}

__device__ __forceinline__ void gemm_compute(
    const __half* Ah, const __half* Bh, const __half* Bl,
    int m0, int n0, unsigned sb, int tid, float acc[2][8][4])
{
    const int lane = tid & 31, wid = tid >> 5;
    const int wm = wid & 3, wn = wid >> 2;

    gemm_load_stage(sb,            Ah, Bh, Bl, m0, n0, 0,  tid); CP_COMMIT();
    gemm_load_stage(sb + G_STAGE,  Ah, Bh, Bl, m0, n0, 32, tid); CP_COMMIT();

    for (int it = 0; it < 32; ++it) {
        CP_WAIT1();
        __syncthreads();
        if (it + 2 < 32)
            gemm_load_stage(sb + ((it + 2) % 3) * G_STAGE, Ah, Bh, Bl,
                            m0, n0, (it + 2) * 32, tid);
        CP_COMMIT();
        const unsigned st = sb + (it % 3) * G_STAGE;
        #pragma unroll
        for (int ks = 0; ks < 2; ++ks) {
            unsigned aH[2][4];
            #pragma unroll
            for (int mt = 0; mt < 2; ++mt) {
                int row = wm * 32 + mt * 16 + (lane & 15);
                int kc  = 2 * ks + (lane >> 4);
                unsigned off = row * 64 + (((kc ^ ((row >> 1) & 3))) << 4);
                LDSM4(aH[mt], st + off);
            }
            #pragma unroll
            for (int q = 0; q < 4; ++q) {
                unsigned bH[4], bL[4];
                int row = wn * 64 + q * 16 + (lane & 7) + 8 * ((lane >> 4) & 1);
                int kc  = 2 * ks + ((lane >> 3) & 1);
                unsigned off = row * 64 + (((kc ^ ((row >> 1) & 3))) << 4);
                LDSM4(bH, st + 8192  + off);
                LDSM4(bL, st + 16384 + off);
                // 8 MMAs, term-major (RAW gap 4)
                MMA4F(acc[0][2*q],   aH[0], bH[0], bH[1]);
                MMA4F(acc[1][2*q],   aH[1], bH[0], bH[1]);
                MMA4F(acc[0][2*q+1], aH[0], bH[2], bH[3]);
                MMA4F(acc[1][2*q+1], aH[1], bH[2], bH[3]);
                MMA4F(acc[0][2*q],   aH[0], bL[0], bL[1]);
                MMA4F(acc[1][2*q],   aH[1], bL[0], bL[1]);
                MMA4F(acc[0][2*q+1], aH[0], bL[2], bL[3]);
                MMA4F(acc[1][2*q+1], aH[1], bL[2], bL[3]);
            }
        }
    }
}

// ---------------- QKV projection: grid (8, 32, 3), 256 thr -----------------
__global__ void __launch_bounds__(256, 2) tc_qkv(
    const float* __restrict__ bq, const float* __restrict__ bk,
    const float* __restrict__ bv)
{
    extern __shared__ char smem[];
    const unsigned sb = smem_u32(smem);
    const int z = blockIdx.z;
    const __half *Ah, *Bh, *Bl;
    __half *dh, *dl;
    const float* bias;
    float scale;
    if (z == 0)      { Ah=g_qh; Bh=g_wqh; Bl=g_wql; dh=g_pq;      dl=0;         bias=bq; scale=0.18033688f; }
    else if (z == 1) { Ah=g_kh; Bh=g_wkh; Bl=g_wkl; dh=g_pkv[0];  dl=g_pkv[1];  bias=bk; scale=1.0f; }
    else             { Ah=g_vh; Bh=g_wvh; Bl=g_wvl; dh=g_pkv[2];  dl=g_pkv[3];  bias=bv; scale=1.0f; }

    const int n0 = blockIdx.x * 128, m0 = blockIdx.y * 128;
    const int tid = threadIdx.x, lane = tid & 31, wid = tid >> 5;
    const int wm = wid & 3, wn = wid >> 2;

    float acc[2][8][4] = {};
    gemm_compute(Ah, Bh, Bl, m0, n0, sb, tid, acc);

    #pragma unroll
    for (int nt = 0; nt < 8; ++nt) {
        int n = n0 + wn * 64 + nt * 8 + (lane & 3) * 2;
        float b0v = bias[n], b1v = bias[n + 1];
        int hd = n >> 6, d = n & 63;
        #pragma unroll
        for (int mt = 0; mt < 2; ++mt) {
            #pragma unroll
            for (int half = 0; half < 2; ++half) {
                int m = m0 + wm * 32 + mt * 16 + (lane >> 2) + 8 * half;
                float x = (acc[mt][nt][2*half+0] + b0v) * scale;
                float y = (acc[mt][nt][2*half+1] + b1v) * scale;
                size_t dst = ((size_t)((m >> 11) * NHEAD + hd) * SEQ + (m & (SEQ-1))) * DK + d;
                if (dl) {
                    unsigned hi, lo; split2h(x, y, hi, lo);
                    *(unsigned*)(dh + dst) = hi;
                    *(unsigned*)(dl + dst) = lo;
                } else {
                    *(unsigned*)(dh + dst) = pack_h2(x, y);
                }
            }
        }
    }
}

// ---------------- output projection: grid (8, 32), 256 thr -----------------
__global__ void __launch_bounds__(256, 2) tc_out(
    const float* __restrict__ bias, float* __restrict__ out)
{
    extern __shared__ char smem[];
    const unsigned sb = smem_u32(smem);
    const int n0 = blockIdx.x * 128, m0 = blockIdx.y * 128;
    const int tid = threadIdx.x, lane = tid & 31, wid = tid >> 5;
    const int wm = wid & 3, wn = wid >> 2;

    float acc[2][8][4] = {};
    gemm_compute(g_po, g_woh, g_wol, m0, n0, sb, tid, acc);

    #pragma unroll
    for (int nt = 0; nt < 8; ++nt) {
        int n = n0 + wn * 64 + nt * 8 + (lane & 3) * 2;
        float b0v = bias[n], b1v = bias[n + 1];
        #pragma unroll
        for (int mt = 0; mt < 2; ++mt) {
            #pragma unroll
            for (int half = 0; half < 2; ++half) {
                int m = m0 + wm * 32 + mt * 16 + (lane >> 2) + 8 * half;
                float2 vv = make_float2(acc[mt][nt][2*half+0] + b0v,
                                        acc[mt][nt][2*half+1] + b1v);
                *(float2*)(out + (size_t)m * D_MODEL + n) = vv;
            }
        }
    }
}

// ---------------- flash attention on HMMA: grid (32, 16, 2), 128 thr -------
// Br=64 (warp w owns rows 16w..16w+15), Bc=32, 64 KV tiles.
// S = Qh*Kh + Qh*Kl ; O += Ph*Vh + Ph*Vl  (A-side plain fp16).
// Q fragments in registers. SMEM: 3 KV stages x 16KB = 48KB.
#define A_STAGE 16384
#define A_SMEM  (3*A_STAGE)

__device__ __forceinline__ void attn_load_stage(
    unsigned st, const __half* kvbase, int tid)
{
    #pragma unroll
    for (int tt = 0; tt < 4; ++tt) {
        const __half* s = kvbase + (size_t)tt * NELEM;
        #pragma unroll
        for (int i = 0; i < 2; ++i) {
            int idx = tid + i * 128;         // 0..255 chunks (32 rows x 8)
            int row = idx >> 3, dc = idx & 7;
            unsigned d = st + tt * 4096 + row * 128 + (((dc ^ (row & 7))) << 4);
            cp16(d, s + (size_t)row * DK + dc * 8);
        }
    }
}

__global__ void __launch_bounds__(128, 3) attn_mma() {
    extern __shared__ char smem[];
    const unsigned sb = smem_u32(smem);
    const int tid = threadIdx.x, lane = tid & 31, w = tid >> 5;
    const int qt = blockIdx.x, h = blockIdx.y, b = blockIdx.z;

    const size_t headoff = ((size_t)(b * NHEAD + h)) * SEQ * DK;
    const __half* qbase  = g_pq + headoff + (size_t)qt * 64 * DK;
    const __half* kvbase = &g_pkv[0][0] + headoff;

    // ---- prologue: stage Q (hi only) through stage-0, park frags in regs ---
    #pragma unroll
    for (int i = 0; i < 4; ++i) {
        int idx = tid + i * 128;             // 0..511 (64 rows x 8)
        int row = idx >> 3, dc = idx & 7;
        cp16(sb + row * 128 + (((dc ^ (row & 7))) << 4),
             qbase + (size_t)row * DK + dc * 8);
    }
    CP_COMMIT(); CP_WAIT0();
    __syncthreads();

    unsigned qh_f[4][4];
    #pragma unroll
    for (int ks = 0; ks < 4; ++ks) {
        int row = 16 * w + (lane & 15);
        int dc  = 2 * ks + (lane >> 4);
        unsigned off = row * 128 + (((dc ^ (row & 7))) << 4);
        LDSM4(qh_f[ks], sb + off);
    }
    __syncthreads();   // stage-0 free before KV pipeline reuses it

    attn_load_stage(sb,           kvbase, tid);            CP_COMMIT();
    attn_load_stage(sb + A_STAGE, kvbase + 32 * DK, tid);  CP_COMMIT();

    float s_m[2] = {-1e30f, -1e30f}, s_l[2] = {0.f, 0.f};
    float o[8][4] = {};

    for (int t = 0; t < 64; ++t) {
        CP_WAIT1();
        __syncthreads();
        if (t + 2 < 64)
            attn_load_stage(sb + ((t + 2) % 3) * A_STAGE,
                            kvbase + (size_t)(t + 2) * 32 * DK, tid);
        CP_COMMIT();
        const unsigned st = sb + (t % 3) * A_STAGE;

        // ---- S = Qh Kh^T + Qh Kl^T (Q pre-scaled by 0.125*log2e) ----
        float s[4][4] = {};
        #pragma unroll
        for (int ks = 0; ks < 4; ++ks) {
            unsigned bh[2][4], bl[2][4];
            #pragma unroll
            for (int q4 = 0; q4 < 2; ++q4) {
                int krow = q4 * 16 + (lane & 7) + 8 * ((lane >> 4) & 1);
                int kdc  = 2 * ks + ((lane >> 3) & 1);
                unsigned off = krow * 128 + (((kdc ^ (krow & 7))) << 4);
                LDSM4(bh[q4], st + off);
                LDSM4(bl[q4], st + 4096 + off);
            }
            // term-major over 4 accumulators (RAW gap 4)
            MMA4F(s[0], qh_f[ks], bh[0][0], bh[0][1]);
            MMA4F(s[1], qh_f[ks], bh[0][2], bh[0][3]);
            MMA4F(s[2], qh_f[ks], bh[1][0], bh[1][1]);
            MMA4F(s[3], qh_f[ks], bh[1][2], bh[1][3]);
            MMA4F(s[0], qh_f[ks], bl[0][0], bl[0][1]);
            MMA4F(s[1], qh_f[ks], bl[0][2], bl[0][3]);
            MMA4F(s[2], qh_f[ks], bl[1][0], bl[1][1]);
            MMA4F(s[3], qh_f[ks], bl[1][2], bl[1][3]);
        }

        // ---- online softmax (base-2 domain) ----
        #pragma unroll
        for (int r = 0; r < 2; ++r) {
            float mx = -1e30f;
            #pragma unroll
            for (int nt = 0; nt < 4; ++nt)
                mx = fmaxf(mx, fmaxf(s[nt][2*r], s[nt][2*r+1]));
            mx = fmaxf(mx, __shfl_xor_sync(0xffffffffu, mx, 1));
            mx = fmaxf(mx, __shfl_xor_sync(0xffffffffu, mx, 2));
            float mnew  = fmaxf(s_m[r], mx);
            float alpha = fexp2(s_m[r] - mnew);
            float rs = 0.f;
            #pragma unroll
            for (int nt = 0; nt < 4; ++nt) {
                float p0 = fexp2(s[nt][2*r]   - mnew);
                float p1 = fexp2(s[nt][2*r+1] - mnew);
                s[nt][2*r] = p0; s[nt][2*r+1] = p1;
                rs += p0 + p1;
            }
            rs += __shfl_xor_sync(0xffffffffu, rs, 1);
            rs += __shfl_xor_sync(0xffffffffu, rs, 2);
            s_l[r] = s_l[r] * alpha + rs;
            s_m[r] = mnew;
            #pragma unroll
            for (int nt = 0; nt < 8; ++nt) { o[nt][2*r] *= alpha; o[nt][2*r+1] *= alpha; }
        }

        // ---- O += Ph Vh + Ph Vl (P packed to fp16, hi only) ----
        #pragma unroll
        for (int ks = 0; ks < 2; ++ks) {
            unsigned pa[4];
            #pragma unroll
            for (int e = 0; e < 4; ++e) {
                int nt = 2 * ks + (e >> 1);
                pa[e] = pack_h2(s[nt][(e & 1) * 2], s[nt][(e & 1) * 2 + 1]);
            }
            #pragma unroll
            for (int dd = 0; dd < 4; dd += 2) {
                unsigned vh0[4], vl0[4], vh1[4], vl1[4];
                int vrow = 16 * ks + (lane & 15);
                {
                    int vdc = 2 * dd + (lane >> 4);
                    unsigned off = vrow * 128 + (((vdc ^ (vrow & 7))) << 4);
                    LDSM4T(vh0, st + 8192  + off);
                    LDSM4T(vl0, st + 12288 + off);
                }
                {
                    int vdc = 2 * (dd + 1) + (lane >> 4);
                    unsigned off = vrow * 128 + (((vdc ^ (vrow & 7))) << 4);
                    LDSM4T(vh1, st + 8192  + off);
                    LDSM4T(vl1, st + 12288 + off);
                }
                MMA4F(o[2*dd],   pa, vh0[0], vh0[1]);
                MMA4F(o[2*dd+1], pa, vh0[2], vh0[3]);
                MMA4F(o[2*dd+2], pa, vh1[0], vh1[1]);
                MMA4F(o[2*dd+3], pa, vh1[2], vh1[3]);
                MMA4F(o[2*dd],   pa, vl0[0], vl0[1]);
                MMA4F(o[2*dd+1], pa, vl0[2], vl0[3]);
                MMA4F(o[2*dd+2], pa, vl1[0], vl1[1]);
                MMA4F(o[2*dd+3], pa, vl1[2], vl1[3]);
            }
        }
    }

    // ---- epilogue: O/l, fp16 hi only at [b][s][h*64+d] ----
    float inv[2] = {1.f / s_l[0], 1.f / s_l[1]};
    #pragma unroll
    for (int nt = 0; nt < 8; ++nt) {
        int d = h * DK + nt * 8 + (lane & 3) * 2;
        #pragma unroll
        for (int r = 0; r < 2; ++r) {
            int srow = qt * 64 + 16 * w + (lane >> 2) + 8 * r;
            size_t dst = (size_t)(b * SEQ + srow) * D_MODEL + d;
            *(unsigned*)(g_po + dst) =
                pack_h2(o[nt][2*r] * inv[r], o[nt][2*r+1] * inv[r]);
        }
    }
}

// ---------------- launcher --------------------------------------------------
extern "C" void kernel_launch(void* const* d_in, const int* in_sizes, int n_in,
                              void* d_out, int out_size) {
    const float* query = (const float*)d_in[0];
    const float* key   = (const float*)d_in[1];
    const float* value = (const float*)d_in[2];
    const float* Wq    = (const float*)d_in[3];
    const float* bq    = (const float*)d_in[4];
    const float* Wk    = (const float*)d_in[5];
    const float* bk    = (const float*)d_in[6];
    const float* Wv    = (const float*)d_in[7];
    const float* bv    = (const float*)d_in[8];
    const float* Wo    = (const float*)d_in[9];
    const float* bo    = (const float*)d_in[10];
    float* out = (float*)d_out;

    cudaFuncSetAttribute(tc_qkv,   cudaFuncAttributeMaxDynamicSharedMemorySize, G_SMEM);
    cudaFuncSetAttribute(tc_out,   cudaFuncAttributeMaxDynamicSharedMemorySize, G_SMEM);
    cudaFuncSetAttribute(attn_mma, cudaFuncAttributeMaxDynamicSharedMemorySize, A_SMEM);

    dim3 gS(592, 7);
    split_all<<<gS, 256>>>(query, key, value, Wq, Wk, Wv, Wo);

    dim3 gQKV(D_MODEL / 128, MTOT / 128, 3);   // (8, 32, 3)
    tc_qkv<<<gQKV, 256, G_SMEM>>>(bq, bk, bv);

    dim3 gAtt(SEQ / 64, NHEAD, BATCH);         // (32, 16, 2)
    attn_mma<<<gAtt, 128, A_SMEM>>>();

    dim3 gOut(D_MODEL / 128, MTOT / 128, 1);   // (8, 32)
    tc_out<<<gOut, 256, G_SMEM>>>(bo, out);
}

// round 15
// speedup vs baseline: 1.7868x; 1.0860x over previous
#include <cuda_runtime.h>
#include <cuda_fp16.h>
#include <stdint.h>

#define D_MODEL 1024
#define NHEAD   16
#define DK      64
#define BATCH   2
#define SEQ     2048
#define MTOT    (BATCH*SEQ)   // 4096
#define NELEM   ((size_t)MTOT*D_MODEL)
#define NW      ((size_t)D_MODEL*D_MODEL)

// ---------------- scratch (static device globals; no allocations) ----------
// activations: fp16 hi only (A-side of their GEMMs)
__device__ __half g_qh[NELEM], g_kh[NELEM], g_vh[NELEM];
// weights: fp16 hi+lo (B-side)
__device__ __half g_wqh[NW], g_wql[NW];
__device__ __half g_wkh[NW], g_wkl[NW];
__device__ __half g_wvh[NW], g_wvl[NW];
__device__ __half g_woh[NW], g_wol[NW];
// projected tensors, head-major [b][h][s][d]
__device__ __half g_pq [NELEM];            // Q hi only (pre-scaled 0.125*log2e)
__device__ __half g_pkv[3][NELEM];         // Kh, Kl, Vh   (V-lo dropped)
__device__ __half g_po [NELEM];            // attn out hi only [b][s][h*64+d]

// ======================= low-level helpers (base ISA only) ================
__device__ __forceinline__ unsigned smem_u32(const void* p) {
    unsigned a;
    asm("{ .reg .u64 t; cvta.to.shared.u64 t, %1; cvt.u32.u64 %0, t; }" : "=r"(a) : "l"(p));
    return a;
}
__device__ __forceinline__ void cp16(unsigned dst, const void* src) {
    asm volatile("cp.async.cg.shared.global [%0], [%1], 16;" :: "r"(dst), "l"(src));
}
#define CP_COMMIT() asm volatile("cp.async.commit_group;" ::: "memory")
#define CP_WAIT1()  asm volatile("cp.async.wait_group 1;"  ::: "memory")
#define CP_WAIT0()  asm volatile("cp.async.wait_group 0;"  ::: "memory")

#define LDSM4(r, a) \
    asm volatile("ldmatrix.sync.aligned.m8n8.x4.shared.b16 {%0,%1,%2,%3}, [%4];" \
        : "=r"((r)[0]), "=r"((r)[1]), "=r"((r)[2]), "=r"((r)[3]) : "r"(a))
#define LDSM4T(r, a) \
    asm volatile("ldmatrix.sync.aligned.m8n8.x4.trans.shared.b16 {%0,%1,%2,%3}, [%4];" \
        : "=r"((r)[0]), "=r"((r)[1]), "=r"((r)[2]), "=r"((r)[3]) : "r"(a))

// fp16 inputs, f32 accumulate
#define MMA4F(d, a, b0, b1) \
    asm volatile("mma.sync.aligned.m16n8k16.row.col.f32.f16.f16.f32 " \
        "{%0,%1,%2,%3}, {%4,%5,%6,%7}, {%8,%9}, {%0,%1,%2,%3};" \
        : "+f"((d)[0]), "+f"((d)[1]), "+f"((d)[2]), "+f"((d)[3]) \
        : "r"((a)[0]), "r"((a)[1]), "r"((a)[2]), "r"((a)[3]), "r"(b0), "r"(b1))

__device__ __forceinline__ float fexp2(float x) {
    float y; asm("ex2.approx.f32 %0, %1;" : "=f"(y) : "f"(x)); return y;
}
__device__ __forceinline__ unsigned pack_h2(float x, float y) {
    __half2 h = __float22half2_rn(make_float2(x, y));
    return *(unsigned*)&h;
}
__device__ __forceinline__ void split2h(float x, float y, unsigned& hi, unsigned& lo) {
    __half2 h = __float22half2_rn(make_float2(x, y));
    float2 hf = __half22float2(h);
    __half2 l = __float22half2_rn(make_float2(x - hf.x, y - hf.y));
    hi = *(unsigned*)&h; lo = *(unsigned*)&l;
}

// ======================= split kernel ======================================
// z<3: activations -> fp16 hi only. z>=3: weights -> fp16 hi+lo.
__global__ __launch_bounds__(256) void split_all(
    const float* q, const float* k, const float* v,
    const float* wq, const float* wk, const float* wv, const float* wo)
{
    const int z = blockIdx.y;
    const float* src; __half *dh, *dl = 0; int n4;
    const int NA4 = MTOT*D_MODEL/4, NW4 = D_MODEL*D_MODEL/4;
    switch (z) {
        case 0: src = q;  dh = g_qh;  n4 = NA4; break;
        case 1: src = k;  dh = g_kh;  n4 = NA4; break;
        case 2: src = v;  dh = g_vh;  n4 = NA4; break;
        case 3: src = wq; dh = g_wqh; dl = g_wql; n4 = NW4; break;
        case 4: src = wk; dh = g_wkh; dl = g_wkl; n4 = NW4; break;
        case 5: src = wv; dh = g_wvh; dl = g_wvl; n4 = NW4; break;
        default:src = wo; dh = g_woh; dl = g_wol; n4 = NW4; break;
    }
    if (z < 3) {
        for (int i = blockIdx.x * blockDim.x + threadIdx.x; i < n4; i += gridDim.x * blockDim.x) {
            float4 vv = ((const float4*)src)[i];
            uint2 o;
            o.x = pack_h2(vv.x, vv.y);
            o.y = pack_h2(vv.z, vv.w);
            ((uint2*)dh)[i] = o;
        }
    } else {
        for (int i = blockIdx.x * blockDim.x + threadIdx.x; i < n4; i += gridDim.x * blockDim.x) {
            float4 vv = ((const float4*)src)[i];
            unsigned h0, l0, h1, l1;
            split2h(vv.x, vv.y, h0, l0);
            split2h(vv.z, vv.w, h1, l1);
            ((unsigned*)dh)[2*i] = h0; ((unsigned*)dh)[2*i+1] = h1;
            ((unsigned*)dl)[2*i] = l0; ((unsigned*)dl)[2*i+1] = l1;
        }
    }
}

// ======================= HMMA GEMM core (2-term fp16 split) ================
// C = Ah*Bh + Ah*Bl. BM=BN=128, BK=32, 256 thr (8 warps = 4x2),
// warp tile 32x64, 3 stages. Stage 24KB: Ah@0, Bh@8K, Bl@16K.
#define G_STAGE 24576
#define G_SMEM  (3*G_STAGE)

__device__ __forceinline__ void gemm_load_stage(
    unsigned st, const __half* Ah, const __half* Bh, const __half* Bl,
    int m0, int n0, int k0, int tid)
{
    const __half* srcs[3] = {Ah, Bh, Bl};
    #pragma unroll
    for (int tt = 0; tt < 3; ++tt) {
        const int r0 = (tt == 0) ? m0 : n0;
        const __half* s = srcs[tt];
        #pragma unroll
        for (int i = 0; i < 2; ++i) {
            int idx = tid + i * 256;
            int row = idx >> 2, kc = idx & 3;
            unsigned d = st + tt * 8192 + row * 64 + (((kc ^ ((row >> 1) & 3))) << 4);
            cp16(d, s + (size_t)(r0 + row) * D_MODEL + k0 + kc * 8);
        }
    }
}

__device__ __forceinline__ void gemm_compute(
    const __half* Ah, const __half* Bh, const __half* Bl,
    int m0, int n0, unsigned sb, int tid, float acc[2][8][4])
{
    const int lane = tid & 31, wid = tid >> 5;
    const int wm = wid & 3, wn = wid >> 2;

    gemm_load_stage(sb,            Ah, Bh, Bl, m0, n0, 0,  tid); CP_COMMIT();
    gemm_load_stage(sb + G_STAGE,  Ah, Bh, Bl, m0, n0, 32, tid); CP_COMMIT();

    for (int it = 0; it < 32; ++it) {
        CP_WAIT1();
        __syncthreads();
        if (it + 2 < 32)
            gemm_load_stage(sb + ((it + 2) % 3) * G_STAGE, Ah, Bh, Bl,
                            m0, n0, (it + 2) * 32, tid);
        CP_COMMIT();
        const unsigned st = sb + (it % 3) * G_STAGE;
        #pragma unroll
        for (int ks = 0; ks < 2; ++ks) {
            unsigned aH[2][4];
            #pragma unroll
            for (int mt = 0; mt < 2; ++mt) {
                int row = wm * 32 + mt * 16 + (lane & 15);
                int kc  = 2 * ks + (lane >> 4);
                unsigned off = row * 64 + (((kc ^ ((row >> 1) & 3))) << 4);
                LDSM4(aH[mt], st + off);
            }
            #pragma unroll
            for (int q = 0; q < 4; ++q) {
                unsigned bH[4], bL[4];
                int row = wn * 64 + q * 16 + (lane & 7) + 8 * ((lane >> 4) & 1);
                int kc  = 2 * ks + ((lane >> 3) & 1);
                unsigned off = row * 64 + (((kc ^ ((row >> 1) & 3))) << 4);
                LDSM4(bH, st + 8192  + off);
                LDSM4(bL, st + 16384 + off);
                // 8 MMAs, term-major (RAW gap 4)
                MMA4F(acc[0][2*q],   aH[0], bH[0], bH[1]);
                MMA4F(acc[1][2*q],   aH[1], bH[0], bH[1]);
                MMA4F(acc[0][2*q+1], aH[0], bH[2], bH[3]);
                MMA4F(acc[1][2*q+1], aH[1], bH[2], bH[3]);
                MMA4F(acc[0][2*q],   aH[0], bL[0], bL[1]);
                MMA4F(acc[1][2*q],   aH[1], bL[0], bL[1]);
                MMA4F(acc[0][2*q+1], aH[0], bL[2], bL[3]);
                MMA4F(acc[1][2*q+1], aH[1], bL[2], bL[3]);
            }
        }
    }
}

// ---------------- QKV projection: grid (8, 32, 3), 256 thr -----------------
__global__ void __launch_bounds__(256, 2) tc_qkv(
    const float* __restrict__ bq, const float* __restrict__ bk,
    const float* __restrict__ bv)
{
    extern __shared__ char smem[];
    const unsigned sb = smem_u32(smem);
    const int z = blockIdx.z;
    const __half *Ah, *Bh, *Bl;
    __half *dh, *dl;
    const float* bias;
    float scale;
    if (z == 0)      { Ah=g_qh; Bh=g_wqh; Bl=g_wql; dh=g_pq;     dl=0;        bias=bq; scale=0.18033688f; }
    else if (z == 1) { Ah=g_kh; Bh=g_wkh; Bl=g_wkl; dh=g_pkv[0]; dl=g_pkv[1]; bias=bk; scale=1.0f; }
    else             { Ah=g_vh; Bh=g_wvh; Bl=g_wvl; dh=g_pkv[2]; dl=0;        bias=bv; scale=1.0f; }

    const int n0 = blockIdx.x * 128, m0 = blockIdx.y * 128;
    const int tid = threadIdx.x, lane = tid & 31, wid = tid >> 5;
    const int wm = wid & 3, wn = wid >> 2;

    float acc[2][8][4] = {};
    gemm_compute(Ah, Bh, Bl, m0, n0, sb, tid, acc);

    #pragma unroll
    for (int nt = 0; nt < 8; ++nt) {
        int n = n0 + wn * 64 + nt * 8 + (lane & 3) * 2;
        float b0v = bias[n], b1v = bias[n + 1];
        int hd = n >> 6, d = n & 63;
        #pragma unroll
        for (int mt = 0; mt < 2; ++mt) {
            #pragma unroll
            for (int half = 0; half < 2; ++half) {
                int m = m0 + wm * 32 + mt * 16 + (lane >> 2) + 8 * half;
                float x = (acc[mt][nt][2*half+0] + b0v) * scale;
                float y = (acc[mt][nt][2*half+1] + b1v) * scale;
                size_t dst = ((size_t)((m >> 11) * NHEAD + hd) * SEQ + (m & (SEQ-1))) * DK + d;
                if (dl) {
                    unsigned hi, lo; split2h(x, y, hi, lo);
                    *(unsigned*)(dh + dst) = hi;
                    *(unsigned*)(dl + dst) = lo;
                } else {
                    *(unsigned*)(dh + dst) = pack_h2(x, y);
                }
            }
        }
    }
}

// ---------------- output projection: grid (8, 32), 256 thr -----------------
__global__ void __launch_bounds__(256, 2) tc_out(
    const float* __restrict__ bias, float* __restrict__ out)
{
    extern __shared__ char smem[];
    const unsigned sb = smem_u32(smem);
    const int n0 = blockIdx.x * 128, m0 = blockIdx.y * 128;
    const int tid = threadIdx.x, lane = tid & 31, wid = tid >> 5;
    const int wm = wid & 3, wn = wid >> 2;

    float acc[2][8][4] = {};
    gemm_compute(g_po, g_woh, g_wol, m0, n0, sb, tid, acc);

    #pragma unroll
    for (int nt = 0; nt < 8; ++nt) {
        int n = n0 + wn * 64 + nt * 8 + (lane & 3) * 2;
        float b0v = bias[n], b1v = bias[n + 1];
        #pragma unroll
        for (int mt = 0; mt < 2; ++mt) {
            #pragma unroll
            for (int half = 0; half < 2; ++half) {
                int m = m0 + wm * 32 + mt * 16 + (lane >> 2) + 8 * half;
                float2 vv = make_float2(acc[mt][nt][2*half+0] + b0v,
                                        acc[mt][nt][2*half+1] + b1v);
                *(float2*)(out + (size_t)m * D_MODEL + n) = vv;
            }
        }
    }
}

// ---------------- flash attention on HMMA: grid (32, 16, 2), 128 thr -------
// Br=64 (warp w owns rows 16w..16w+15), Bc=32, 64 KV tiles.
// S = Qh*Kh + Qh*Kl ; O += Ph*Vh (V-lo dropped).
// Q fragments in registers. SMEM: 3 stages x 12KB (Kh@0,Kl@4K,Vh@8K) = 36KB
// -> 4 CTA/SM (launch_bounds(128,4)).
#define A_STAGE 12288
#define A_SMEM  (3*A_STAGE)

__device__ __forceinline__ void attn_load_stage(
    unsigned st, const __half* kvbase, int tid)
{
    #pragma unroll
    for (int tt = 0; tt < 3; ++tt) {
        const __half* s = kvbase + (size_t)tt * NELEM;
        #pragma unroll
        for (int i = 0; i < 2; ++i) {
            int idx = tid + i * 128;         // 0..255 chunks (32 rows x 8)
            int row = idx >> 3, dc = idx & 7;
            unsigned d = st + tt * 4096 + row * 128 + (((dc ^ (row & 7))) << 4);
            cp16(d, s + (size_t)row * DK + dc * 8);
        }
    }
}

__global__ void __launch_bounds__(128, 4) attn_mma() {
    extern __shared__ char smem[];
    const unsigned sb = smem_u32(smem);
    const int tid = threadIdx.x, lane = tid & 31, w = tid >> 5;
    const int qt = blockIdx.x, h = blockIdx.y, b = blockIdx.z;

    const size_t headoff = ((size_t)(b * NHEAD + h)) * SEQ * DK;
    const __half* qbase  = g_pq + headoff + (size_t)qt * 64 * DK;
    const __half* kvbase = &g_pkv[0][0] + headoff;

    // ---- prologue: stage Q (hi only) through stage-0, park frags in regs ---
    #pragma unroll
    for (int i = 0; i < 4; ++i) {
        int idx = tid + i * 128;             // 0..511 (64 rows x 8)
        int row = idx >> 3, dc = idx & 7;
        cp16(sb + row * 128 + (((dc ^ (row & 7))) << 4),
             qbase + (size_t)row * DK + dc * 8);
    }
    CP_COMMIT(); CP_WAIT0();
    __syncthreads();

    unsigned qh_f[4][4];
    #pragma unroll
    for (int ks = 0; ks < 4; ++ks) {
        int row = 16 * w + (lane & 15);
        int dc  = 2 * ks + (lane >> 4);
        unsigned off = row * 128 + (((dc ^ (row & 7))) << 4);
        LDSM4(qh_f[ks], sb + off);
    }
    __syncthreads();   // stage-0 free before KV pipeline reuses it

    attn_load_stage(sb,           kvbase, tid);            CP_COMMIT();
    attn_load_stage(sb + A_STAGE, kvbase + 32 * DK, tid);  CP_COMMIT();

    float s_m[2] = {-1e30f, -1e30f}, s_l[2] = {0.f, 0.f};
    float o[8][4] = {};

    for (int t = 0; t < 64; ++t) {
        CP_WAIT1();
        __syncthreads();
        if (t + 2 < 64)
            attn_load_stage(sb + ((t + 2) % 3) * A_STAGE,
                            kvbase + (size_t)(t + 2) * 32 * DK, tid);
        CP_COMMIT();
        const unsigned st = sb + (t % 3) * A_STAGE;

        // ---- S = Qh Kh^T + Qh Kl^T (Q pre-scaled by 0.125*log2e) ----
        float s[4][4] = {};
        #pragma unroll
        for (int ks = 0; ks < 4; ++ks) {
            unsigned bh[2][4], bl[2][4];
            #pragma unroll
            for (int q4 = 0; q4 < 2; ++q4) {
                int krow = q4 * 16 + (lane & 7) + 8 * ((lane >> 4) & 1);
                int kdc  = 2 * ks + ((lane >> 3) & 1);
                unsigned off = krow * 128 + (((kdc ^ (krow & 7))) << 4);
                LDSM4(bh[q4], st + off);
                LDSM4(bl[q4], st + 4096 + off);
            }
            // term-major over 4 accumulators (RAW gap 4)
            MMA4F(s[0], qh_f[ks], bh[0][0], bh[0][1]);
            MMA4F(s[1], qh_f[ks], bh[0][2], bh[0][3]);
            MMA4F(s[2], qh_f[ks], bh[1][0], bh[1][1]);
            MMA4F(s[3], qh_f[ks], bh[1][2], bh[1][3]);
            MMA4F(s[0], qh_f[ks], bl[0][0], bl[0][1]);
            MMA4F(s[1], qh_f[ks], bl[0][2], bl[0][3]);
            MMA4F(s[2], qh_f[ks], bl[1][0], bl[1][1]);
            MMA4F(s[3], qh_f[ks], bl[1][2], bl[1][3]);
        }

        // ---- online softmax (base-2 domain) ----
        #pragma unroll
        for (int r = 0; r < 2; ++r) {
            float mx = -1e30f;
            #pragma unroll
            for (int nt = 0; nt < 4; ++nt)
                mx = fmaxf(mx, fmaxf(s[nt][2*r], s[nt][2*r+1]));
            mx = fmaxf(mx, __shfl_xor_sync(0xffffffffu, mx, 1));
            mx = fmaxf(mx, __shfl_xor_sync(0xffffffffu, mx, 2));
            float mnew  = fmaxf(s_m[r], mx);
            float alpha = fexp2(s_m[r] - mnew);
            float rs = 0.f;
            #pragma unroll
            for (int nt = 0; nt < 4; ++nt) {
                float p0 = fexp2(s[nt][2*r]   - mnew);
                float p1 = fexp2(s[nt][2*r+1] - mnew);
                s[nt][2*r] = p0; s[nt][2*r+1] = p1;
                rs += p0 + p1;
            }
            rs += __shfl_xor_sync(0xffffffffu, rs, 1);
            rs += __shfl_xor_sync(0xffffffffu, rs, 2);
            s_l[r] = s_l[r] * alpha + rs;
            s_m[r] = mnew;
            #pragma unroll
            for (int nt = 0; nt < 8; ++nt) { o[nt][2*r] *= alpha; o[nt][2*r+1] *= alpha; }
        }

        // ---- O += Ph Vh (single term; P packed to fp16) ----
        #pragma unroll
        for (int ks = 0; ks < 2; ++ks) {
            unsigned pa[4];
            #pragma unroll
            for (int e = 0; e < 4; ++e) {
                int nt = 2 * ks + (e >> 1);
                pa[e] = pack_h2(s[nt][(e & 1) * 2], s[nt][(e & 1) * 2 + 1]);
            }
            #pragma unroll
            for (int dd = 0; dd < 4; dd += 2) {
                unsigned vh0[4], vh1[4];
                int vrow = 16 * ks + (lane & 15);
                {
                    int vdc = 2 * dd + (lane >> 4);
                    unsigned off = vrow * 128 + (((vdc ^ (vrow & 7))) << 4);
                    LDSM4T(vh0, st + 8192 + off);
                }
                {
                    int vdc = 2 * (dd + 1) + (lane >> 4);
                    unsigned off = vrow * 128 + (((vdc ^ (vrow & 7))) << 4);
                    LDSM4T(vh1, st + 8192 + off);
                }
                MMA4F(o[2*dd],   pa, vh0[0], vh0[1]);
                MMA4F(o[2*dd+1], pa, vh0[2], vh0[3]);
                MMA4F(o[2*dd+2], pa, vh1[0], vh1[1]);
                MMA4F(o[2*dd+3], pa, vh1[2], vh1[3]);
            }
        }
    }

    // ---- epilogue: O/l, fp16 hi only at [b][s][h*64+d] ----
    float inv[2] = {1.f / s_l[0], 1.f / s_l[1]};
    #pragma unroll
    for (int nt = 0; nt < 8; ++nt) {
        int d = h * DK + nt * 8 + (lane & 3) * 2;
        #pragma unroll
        for (int r = 0; r < 2; ++r) {
            int srow = qt * 64 + 16 * w + (lane >> 2) + 8 * r;
            size_t dst = (size_t)(b * SEQ + srow) * D_MODEL + d;
            *(unsigned*)(g_po + dst) =
                pack_h2(o[nt][2*r] * inv[r], o[nt][2*r+1] * inv[r]);
        }
    }
}

// ---------------- launcher --------------------------------------------------
extern "C" void kernel_launch(void* const* d_in, const int* in_sizes, int n_in,
                              void* d_out, int out_size) {
    const float* query = (const float*)d_in[0];
    const float* key   = (const float*)d_in[1];
    const float* value = (const float*)d_in[2];
    const float* Wq    = (const float*)d_in[3];
    const float* bq    = (const float*)d_in[4];
    const float* Wk    = (const float*)d_in[5];
    const float* bk    = (const float*)d_in[6];
    const float* Wv    = (const float*)d_in[7];
    const float* bv    = (const float*)d_in[8];
    const float* Wo    = (const float*)d_in[9];
    const float* bo    = (const float*)d_in[10];
    float* out = (float*)d_out;

    cudaFuncSetAttribute(tc_qkv,   cudaFuncAttributeMaxDynamicSharedMemorySize, G_SMEM);
    cudaFuncSetAttribute(tc_out,   cudaFuncAttributeMaxDynamicSharedMemorySize, G_SMEM);
    cudaFuncSetAttribute(attn_mma, cudaFuncAttributeMaxDynamicSharedMemorySize, A_SMEM);

    dim3 gS(592, 7);
    split_all<<<gS, 256>>>(query, key, value, Wq, Wk, Wv, Wo);

    dim3 gQKV(D_MODEL / 128, MTOT / 128, 3);   // (8, 32, 3)
    tc_qkv<<<gQKV, 256, G_SMEM>>>(bq, bk, bv);

    dim3 gAtt(SEQ / 64, NHEAD, BATCH);         // (32, 16, 2)
    attn_mma<<<gAtt, 128, A_SMEM>>>();

    dim3 gOut(D_MODEL / 128, MTOT / 128, 1);   // (8, 32)
    tc_out<<<gOut, 256, G_SMEM>>>(bo, out);
}

// round 16
// speedup vs baseline: 2.2925x; 1.2830x over previous
#include <cuda_runtime.h>
#include <cuda_fp16.h>
#include <stdint.h>

#define D_MODEL 1024
#define NHEAD   16
#define DK      64
#define BATCH   2
#define SEQ     2048
#define MTOT    (BATCH*SEQ)   // 4096
#define NELEM   ((size_t)MTOT*D_MODEL)
#define NW      ((size_t)D_MODEL*D_MODEL)

// ---------------- scratch (static device globals; no allocations) ----------
// activations + weights: fp16 hi only
__device__ __half g_qh[NELEM], g_kh[NELEM], g_vh[NELEM];
__device__ __half g_wqh[NW], g_wkh[NW], g_wvh[NW], g_woh[NW];
// projected tensors, head-major [b][h][s][d]
__device__ __half g_pq [NELEM];            // Q hi (pre-scaled 0.125*log2e)
__device__ __half g_pkv[3][NELEM];         // Kh, Kl, Vh
__device__ __half g_po [NELEM];            // attn out hi [b][s][h*64+d]

// ======================= low-level helpers (base ISA only) ================
__device__ __forceinline__ unsigned smem_u32(const void* p) {
    unsigned a;
    asm("{ .reg .u64 t; cvta.to.shared.u64 t, %1; cvt.u32.u64 %0, t; }" : "=r"(a) : "l"(p));
    return a;
}
__device__ __forceinline__ void cp16(unsigned dst, const void* src) {
    asm volatile("cp.async.cg.shared.global [%0], [%1], 16;" :: "r"(dst), "l"(src));
}
#define CP_COMMIT() asm volatile("cp.async.commit_group;" ::: "memory")
#define CP_WAIT1()  asm volatile("cp.async.wait_group 1;"  ::: "memory")
#define CP_WAIT0()  asm volatile("cp.async.wait_group 0;"  ::: "memory")

#define LDSM4(r, a) \
    asm volatile("ldmatrix.sync.aligned.m8n8.x4.shared.b16 {%0,%1,%2,%3}, [%4];" \
        : "=r"((r)[0]), "=r"((r)[1]), "=r"((r)[2]), "=r"((r)[3]) : "r"(a))
#define LDSM4T(r, a) \
    asm volatile("ldmatrix.sync.aligned.m8n8.x4.trans.shared.b16 {%0,%1,%2,%3}, [%4];" \
        : "=r"((r)[0]), "=r"((r)[1]), "=r"((r)[2]), "=r"((r)[3]) : "r"(a))

// fp16 inputs, f32 accumulate
#define MMA4F(d, a, b0, b1) \
    asm volatile("mma.sync.aligned.m16n8k16.row.col.f32.f16.f16.f32 " \
        "{%0,%1,%2,%3}, {%4,%5,%6,%7}, {%8,%9}, {%0,%1,%2,%3};" \
        : "+f"((d)[0]), "+f"((d)[1]), "+f"((d)[2]), "+f"((d)[3]) \
        : "r"((a)[0]), "r"((a)[1]), "r"((a)[2]), "r"((a)[3]), "r"(b0), "r"(b1))

__device__ __forceinline__ float fexp2(float x) {
    float y; asm("ex2.approx.f32 %0, %1;" : "=f"(y) : "f"(x)); return y;
}
__device__ __forceinline__ unsigned pack_h2(float x, float y) {
    __half2 h = __float22half2_rn(make_float2(x, y));
    return *(unsigned*)&h;
}
__device__ __forceinline__ void split2h(float x, float y, unsigned& hi, unsigned& lo) {
    __half2 h = __float22half2_rn(make_float2(x, y));
    float2 hf = __half22float2(h);
    __half2 l = __float22half2_rn(make_float2(x - hf.x, y - hf.y));
    hi = *(unsigned*)&h; lo = *(unsigned*)&l;
}

// ======================= convert kernel: fp32 -> fp16 =======================
__global__ __launch_bounds__(256) void split_all(
    const float* q, const float* k, const float* v,
    const float* wq, const float* wk, const float* wv, const float* wo)
{
    const int z = blockIdx.y;
    const float* src; __half* dh; int n4;
    const int NA4 = MTOT*D_MODEL/4, NW4 = D_MODEL*D_MODEL/4;
    switch (z) {
        case 0: src = q;  dh = g_qh;  n4 = NA4; break;
        case 1: src = k;  dh = g_kh;  n4 = NA4; break;
        case 2: src = v;  dh = g_vh;  n4 = NA4; break;
        case 3: src = wq; dh = g_wqh; n4 = NW4; break;
        case 4: src = wk; dh = g_wkh; n4 = NW4; break;
        case 5: src = wv; dh = g_wvh; n4 = NW4; break;
        default:src = wo; dh = g_woh; n4 = NW4; break;
    }
    for (int i = blockIdx.x * blockDim.x + threadIdx.x; i < n4; i += gridDim.x * blockDim.x) {
        float4 vv = ((const float4*)src)[i];
        uint2 o;
        o.x = pack_h2(vv.x, vv.y);
        o.y = pack_h2(vv.z, vv.w);
        ((uint2*)dh)[i] = o;
    }
}

// ======================= HMMA GEMM core (plain fp16, f32 accum) ============
// C = Ah*Bh. BM=BN=128, BK=32, 256 thr (8 warps = 4x2), warp tile 32x64,
// 3 stages. Stage 16KB: Ah@0, Bh@8K.
#define G_STAGE 16384
#define G_SMEM  (3*G_STAGE)

__device__ __forceinline__ void gemm_load_stage(
    unsigned st, const __half* Ah, const __half* Bh,
    int m0, int n0, int k0, int tid)
{
    const __half* srcs[2] = {Ah, Bh};
    #pragma unroll
    for (int tt = 0; tt < 2; ++tt) {
        const int r0 = (tt == 0) ? m0 : n0;
        const __half* s = srcs[tt];
        #pragma unroll
        for (int i = 0; i < 2; ++i) {
            int idx = tid + i * 256;
            int row = idx >> 2, kc = idx & 3;
            unsigned d = st + tt * 8192 + row * 64 + (((kc ^ ((row >> 1) & 3))) << 4);
            cp16(d, s + (size_t)(r0 + row) * D_MODEL + k0 + kc * 8);
        }
    }
}

__device__ __forceinline__ void gemm_compute(
    const __half* Ah, const __half* Bh,
    int m0, int n0, unsigned sb, int tid, float acc[2][8][4])
{
    const int lane = tid & 31, wid = tid >> 5;
    const int wm = wid & 3, wn = wid >> 2;

    gemm_load_stage(sb,            Ah, Bh, m0, n0, 0,  tid); CP_COMMIT();
    gemm_load_stage(sb + G_STAGE,  Ah, Bh, m0, n0, 32, tid); CP_COMMIT();

    for (int it = 0; it < 32; ++it) {
        CP_WAIT1();
        __syncthreads();
        if (it + 2 < 32)
            gemm_load_stage(sb + ((it + 2) % 3) * G_STAGE, Ah, Bh,
                            m0, n0, (it + 2) * 32, tid);
        CP_COMMIT();
        const unsigned st = sb + (it % 3) * G_STAGE;
        #pragma unroll
        for (int ks = 0; ks < 2; ++ks) {
            unsigned aH[2][4];
            #pragma unroll
            for (int mt = 0; mt < 2; ++mt) {
                int row = wm * 32 + mt * 16 + (lane & 15);
                int kc  = 2 * ks + (lane >> 4);
                unsigned off = row * 64 + (((kc ^ ((row >> 1) & 3))) << 4);
                LDSM4(aH[mt], st + off);
            }
            #pragma unroll
            for (int q = 0; q < 4; ++q) {
                unsigned bH[4];
                int row = wn * 64 + q * 16 + (lane & 7) + 8 * ((lane >> 4) & 1);
                int kc  = 2 * ks + ((lane >> 3) & 1);
                unsigned off = row * 64 + (((kc ^ ((row >> 1) & 3))) << 4);
                LDSM4(bH, st + 8192 + off);
                MMA4F(acc[0][2*q],   aH[0], bH[0], bH[1]);
                MMA4F(acc[1][2*q],   aH[1], bH[0], bH[1]);
                MMA4F(acc[0][2*q+1], aH[0], bH[2], bH[3]);
                MMA4F(acc[1][2*q+1], aH[1], bH[2], bH[3]);
            }
        }
    }
}

// ---------------- QKV projection: grid (8, 32, 3), 256 thr -----------------
__global__ void __launch_bounds__(256, 2) tc_qkv(
    const float* __restrict__ bq, const float* __restrict__ bk,
    const float* __restrict__ bv)
{
    extern __shared__ char smem[];
    const unsigned sb = smem_u32(smem);
    const int z = blockIdx.z;
    const __half *Ah, *Bh;
    __half *dh, *dl;
    const float* bias;
    float scale;
    if (z == 0)      { Ah=g_qh; Bh=g_wqh; dh=g_pq;     dl=0;        bias=bq; scale=0.18033688f; }
    else if (z == 1) { Ah=g_kh; Bh=g_wkh; dh=g_pkv[0]; dl=g_pkv[1]; bias=bk; scale=1.0f; }
    else             { Ah=g_vh; Bh=g_wvh; dh=g_pkv[2]; dl=0;        bias=bv; scale=1.0f; }

    const int n0 = blockIdx.x * 128, m0 = blockIdx.y * 128;
    const int tid = threadIdx.x, lane = tid & 31, wid = tid >> 5;
    const int wm = wid & 3, wn = wid >> 2;

    float acc[2][8][4] = {};
    gemm_compute(Ah, Bh, m0, n0, sb, tid, acc);

    #pragma unroll
    for (int nt = 0; nt < 8; ++nt) {
        int n = n0 + wn * 64 + nt * 8 + (lane & 3) * 2;
        float b0v = bias[n], b1v = bias[n + 1];
        int hd = n >> 6, d = n & 63;
        #pragma unroll
        for (int mt = 0; mt < 2; ++mt) {
            #pragma unroll
            for (int half = 0; half < 2; ++half) {
                int m = m0 + wm * 32 + mt * 16 + (lane >> 2) + 8 * half;
                float x = (acc[mt][nt][2*half+0] + b0v) * scale;
                float y = (acc[mt][nt][2*half+1] + b1v) * scale;
                size_t dst = ((size_t)((m >> 11) * NHEAD + hd) * SEQ + (m & (SEQ-1))) * DK + d;
                if (dl) {
                    unsigned hi, lo; split2h(x, y, hi, lo);
                    *(unsigned*)(dh + dst) = hi;
                    *(unsigned*)(dl + dst) = lo;
                } else {
                    *(unsigned*)(dh + dst) = pack_h2(x, y);
                }
            }
        }
    }
}

// ---------------- output projection: grid (8, 32), 256 thr -----------------
__global__ void __launch_bounds__(256, 2) tc_out(
    const float* __restrict__ bias, float* __restrict__ out)
{
    extern __shared__ char smem[];
    const unsigned sb = smem_u32(smem);
    const int n0 = blockIdx.x * 128, m0 = blockIdx.y * 128;
    const int tid = threadIdx.x, lane = tid & 31, wid = tid >> 5;
    const int wm = wid & 3, wn = wid >> 2;

    float acc[2][8][4] = {};
    gemm_compute(g_po, g_woh, m0, n0, sb, tid, acc);

    #pragma unroll
    for (int nt = 0; nt < 8; ++nt) {
        int n = n0 + wn * 64 + nt * 8 + (lane & 3) * 2;
        float b0v = bias[n], b1v = bias[n + 1];
        #pragma unroll
        for (int mt = 0; mt < 2; ++mt) {
            #pragma unroll
            for (int half = 0; half < 2; ++half) {
                int m = m0 + wm * 32 + mt * 16 + (lane >> 2) + 8 * half;
                float2 vv = make_float2(acc[mt][nt][2*half+0] + b0v,
                                        acc[mt][nt][2*half+1] + b1v);
                *(float2*)(out + (size_t)m * D_MODEL + n) = vv;
            }
        }
    }
}

// ---------------- flash attention on HMMA: grid (32, 16, 2), 128 thr -------
// Br=64 (warp w owns rows 16w..16w+15), Bc=32, 64 KV tiles.
// S = Qh*Kh + Qh*Kl ; O += Ph*Vh.
// Q fragments in registers. SMEM: 3 stages x 12KB (Kh@0,Kl@4K,Vh@8K) = 36KB.
#define A_STAGE 12288
#define A_SMEM  (3*A_STAGE)

__device__ __forceinline__ void attn_load_stage(
    unsigned st, const __half* kvbase, int tid)
{
    #pragma unroll
    for (int tt = 0; tt < 3; ++tt) {
        const __half* s = kvbase + (size_t)tt * NELEM;
        #pragma unroll
        for (int i = 0; i < 2; ++i) {
            int idx = tid + i * 128;         // 0..255 chunks (32 rows x 8)
            int row = idx >> 3, dc = idx & 7;
            unsigned d = st + tt * 4096 + row * 128 + (((dc ^ (row & 7))) << 4);
            cp16(d, s + (size_t)row * DK + dc * 8);
        }
    }
}

__global__ void __launch_bounds__(128, 4) attn_mma() {
    extern __shared__ char smem[];
    const unsigned sb = smem_u32(smem);
    const int tid = threadIdx.x, lane = tid & 31, w = tid >> 5;
    const int qt = blockIdx.x, h = blockIdx.y, b = blockIdx.z;

    const size_t headoff = ((size_t)(b * NHEAD + h)) * SEQ * DK;
    const __half* qbase  = g_pq + headoff + (size_t)qt * 64 * DK;
    const __half* kvbase = &g_pkv[0][0] + headoff;

    // ---- prologue: stage Q (hi only) through stage-0, park frags in regs ---
    #pragma unroll
    for (int i = 0; i < 4; ++i) {
        int idx = tid + i * 128;             // 0..511 (64 rows x 8)
        int row = idx >> 3, dc = idx & 7;
        cp16(sb + row * 128 + (((dc ^ (row & 7))) << 4),
             qbase + (size_t)row * DK + dc * 8);
    }
    CP_COMMIT(); CP_WAIT0();
    __syncthreads();

    unsigned qh_f[4][4];
    #pragma unroll
    for (int ks = 0; ks < 4; ++ks) {
        int row = 16 * w + (lane & 15);
        int dc  = 2 * ks + (lane >> 4);
        unsigned off = row * 128 + (((dc ^ (row & 7))) << 4);
        LDSM4(qh_f[ks], sb + off);
    }
    __syncthreads();   // stage-0 free before KV pipeline reuses it

    attn_load_stage(sb,           kvbase, tid);            CP_COMMIT();
    attn_load_stage(sb + A_STAGE, kvbase + 32 * DK, tid);  CP_COMMIT();

    float s_m[2] = {-1e30f, -1e30f}, s_l[2] = {0.f, 0.f};
    float o[8][4] = {};

    for (int t = 0; t < 64; ++t) {
        CP_WAIT1();
        __syncthreads();
        if (t + 2 < 64)
            attn_load_stage(sb + ((t + 2) % 3) * A_STAGE,
                            kvbase + (size_t)(t + 2) * 32 * DK, tid);
        CP_COMMIT();
        const unsigned st = sb + (t % 3) * A_STAGE;

        // ---- S = Qh Kh^T + Qh Kl^T (Q pre-scaled by 0.125*log2e) ----
        float s[4][4] = {};
        #pragma unroll
        for (int ks = 0; ks < 4; ++ks) {
            unsigned bh[2][4], bl[2][4];
            #pragma unroll
            for (int q4 = 0; q4 < 2; ++q4) {
                int krow = q4 * 16 + (lane & 7) + 8 * ((lane >> 4) & 1);
                int kdc  = 2 * ks + ((lane >> 3) & 1);
                unsigned off = krow * 128 + (((kdc ^ (krow & 7))) << 4);
                LDSM4(bh[q4], st + off);
                LDSM4(bl[q4], st + 4096 + off);
            }
            MMA4F(s[0], qh_f[ks], bh[0][0], bh[0][1]);
            MMA4F(s[1], qh_f[ks], bh[0][2], bh[0][3]);
            MMA4F(s[2], qh_f[ks], bh[1][0], bh[1][1]);
            MMA4F(s[3], qh_f[ks], bh[1][2], bh[1][3]);
            MMA4F(s[0], qh_f[ks], bl[0][0], bl[0][1]);
            MMA4F(s[1], qh_f[ks], bl[0][2], bl[0][3]);
            MMA4F(s[2], qh_f[ks], bl[1][0], bl[1][1]);
            MMA4F(s[3], qh_f[ks], bl[1][2], bl[1][3]);
        }

        // ---- online softmax (base-2 domain) ----
        #pragma unroll
        for (int r = 0; r < 2; ++r) {
            float mx = -1e30f;
            #pragma unroll
            for (int nt = 0; nt < 4; ++nt)
                mx = fmaxf(mx, fmaxf(s[nt][2*r], s[nt][2*r+1]));
            mx = fmaxf(mx, __shfl_xor_sync(0xffffffffu, mx, 1));
            mx = fmaxf(mx, __shfl_xor_sync(0xffffffffu, mx, 2));
            float mnew  = fmaxf(s_m[r], mx);
            float alpha = fexp2(s_m[r] - mnew);
            float rs = 0.f;
            #pragma unroll
            for (int nt = 0; nt < 4; ++nt) {
                float p0 = fexp2(s[nt][2*r]   - mnew);
                float p1 = fexp2(s[nt][2*r+1] - mnew);
                s[nt][2*r] = p0; s[nt][2*r+1] = p1;
                rs += p0 + p1;
            }
            rs += __shfl_xor_sync(0xffffffffu, rs, 1);
            rs += __shfl_xor_sync(0xffffffffu, rs, 2);
            s_l[r] = s_l[r] * alpha + rs;
            s_m[r] = mnew;
            #pragma unroll
            for (int nt = 0; nt < 8; ++nt) { o[nt][2*r] *= alpha; o[nt][2*r+1] *= alpha; }
        }

        // ---- O += Ph Vh (P packed to fp16) ----
        #pragma unroll
        for (int ks = 0; ks < 2; ++ks) {
            unsigned pa[4];
            #pragma unroll
            for (int e = 0; e < 4; ++e) {
                int nt = 2 * ks + (e >> 1);
                pa[e] = pack_h2(s[nt][(e & 1) * 2], s[nt][(e & 1) * 2 + 1]);
            }
            #pragma unroll
            for (int dd = 0; dd < 4; dd += 2) {
                unsigned vh0[4], vh1[4];
                int vrow = 16 * ks + (lane & 15);
                {
                    int vdc = 2 * dd + (lane >> 4);
                    unsigned off = vrow * 128 + (((vdc ^ (vrow & 7))) << 4);
                    LDSM4T(vh0, st + 8192 + off);
                }
                {
                    int vdc = 2 * (dd + 1) + (lane >> 4);
                    unsigned off = vrow * 128 + (((vdc ^ (vrow & 7))) << 4);
                    LDSM4T(vh1, st + 8192 + off);
                }
                MMA4F(o[2*dd],   pa, vh0[0], vh0[1]);
                MMA4F(o[2*dd+1], pa, vh0[2], vh0[3]);
                MMA4F(o[2*dd+2], pa, vh1[0], vh1[1]);
                MMA4F(o[2*dd+3], pa, vh1[2], vh1[3]);
            }
        }
    }

    // ---- epilogue: O/l, fp16 hi only at [b][s][h*64+d] ----
    float inv[2] = {1.f / s_l[0], 1.f / s_l[1]};
    #pragma unroll
    for (int nt = 0; nt < 8; ++nt) {
        int d = h * DK + nt * 8 + (lane & 3) * 2;
        #pragma unroll
        for (int r = 0; r < 2; ++r) {
            int srow = qt * 64 + 16 * w + (lane >> 2) + 8 * r;
            size_t dst = (size_t)(b * SEQ + srow) * D_MODEL + d;
            *(unsigned*)(g_po + dst) =
                pack_h2(o[nt][2*r] * inv[r], o[nt][2*r+1] * inv[r]);
        }
    }
}

// ---------------- launcher --------------------------------------------------
extern "C" void kernel_launch(void* const* d_in, const int* in_sizes, int n_in,
                              void* d_out, int out_size) {
    const float* query = (const float*)d_in[0];
    const float* key   = (const float*)d_in[1];
    const float* value = (const float*)d_in[2];
    const float* Wq    = (const float*)d_in[3];
    const float* bq    = (const float*)d_in[4];
    const float* Wk    = (const float*)d_in[5];
    const float* bk    = (const float*)d_in[6];
    const float* Wv    = (const float*)d_in[7];
    const float* bv    = (const float*)d_in[8];
    const float* Wo    = (const float*)d_in[9];
    const float* bo    = (const float*)d_in[10];
    float* out = (float*)d_out;

    cudaFuncSetAttribute(tc_qkv,   cudaFuncAttributeMaxDynamicSharedMemorySize, G_SMEM);
    cudaFuncSetAttribute(tc_out,   cudaFuncAttributeMaxDynamicSharedMemorySize, G_SMEM);
    cudaFuncSetAttribute(attn_mma, cudaFuncAttributeMaxDynamicSharedMemorySize, A_SMEM);

    dim3 gS(592, 7);
    split_all<<<gS, 256>>>(query, key, value, Wq, Wk, Wv, Wo);

    dim3 gQKV(D_MODEL / 128, MTOT / 128, 3);   // (8, 32, 3)
    tc_qkv<<<gQKV, 256, G_SMEM>>>(bq, bk, bv);

    dim3 gAtt(SEQ / 64, NHEAD, BATCH);         // (32, 16, 2)
    attn_mma<<<gAtt, 128, A_SMEM>>>();

    dim3 gOut(D_MODEL / 128, MTOT / 128, 1);   // (8, 32)
    tc_out<<<gOut, 256, G_SMEM>>>(bo, out);
}